// round 7
// baseline (speedup 1.0000x reference)
#include <cuda_runtime.h>
#include <cuda_fp16.h>
#include <cstdint>

// ---------------------------------------------------------------------------
#define M_ 16384           // B*S token rows
#define P_ 512             // prototypes (= N)
#define D_ 768             // feature dim (= K)
#define BM 128
#define BN 128
#define BKH 64             // K halves per stage (128 B per row)
#define NS (D_ / BKH)      // 12 stages
#define NTH 512
#define STAGES 3
#define TILEB 16384        // one operand tile: 128 rows x 128 B
#define STAGEB (2 * TILEB)
#define SMEM_BYTES (STAGES * STAGEB + 128)

__device__ __half g_a16[(size_t)M_ * D_];
__device__ __half g_b16[(size_t)P_ * D_];
__device__ float  g_xsq[M_];
__device__ float  g_psq[P_];

// ---------------------------------------------------------------------------
// Prep: one pass over f32 inputs -> fp16 copies + exact f32 row norms.
// Also writes the prototype passthrough (second tuple output).
// Block = 256 thr = 16 rows x 16 lanes; each lane reads 12 float4.
// ---------------------------------------------------------------------------
__global__ void prep_kernel(const float* __restrict__ X,
                            const float* __restrict__ Pp,
                            float* __restrict__ proto_out) {
    const int r   = threadIdx.x >> 4;
    const int kq  = threadIdx.x & 15;
    const int row = blockIdx.x * 16 + r;
    const float* src;
    __half* dst16;
    float* dstn;
    float* passthru = nullptr;
    if (row < M_) {
        src = X + (size_t)row * D_;  dst16 = g_a16 + (size_t)row * D_;  dstn = g_xsq + row;
    } else {
        const int pr = row - M_;
        src = Pp + (size_t)pr * D_;  dst16 = g_b16 + (size_t)pr * D_;   dstn = g_psq + pr;
        passthru = proto_out + (size_t)pr * D_;
    }
    float s = 0.f;
    #pragma unroll
    for (int i = 0; i < 12; i++) {
        float4 v = *reinterpret_cast<const float4*>(src + i * 64 + kq * 4);
        s = fmaf(v.x, v.x, fmaf(v.y, v.y, fmaf(v.z, v.z, fmaf(v.w, v.w, s))));
        __half2 h01 = __floats2half2_rn(v.x, v.y);
        __half2 h23 = __floats2half2_rn(v.z, v.w);
        *reinterpret_cast<uint2*>(dst16 + i * 64 + kq * 4) =
            make_uint2(*reinterpret_cast<uint32_t*>(&h01),
                       *reinterpret_cast<uint32_t*>(&h23));
        if (passthru) *reinterpret_cast<float4*>(passthru + i * 64 + kq * 4) = v;
    }
    #pragma unroll
    for (int o = 8; o; o >>= 1) s += __shfl_xor_sync(0xffffffffu, s, o);
    if (kq == 0) *dstn = s;
}

// ---------------------------------------------------------------------------
__device__ __forceinline__ void cp_async16(uint32_t d, const void* s) {
    asm volatile("cp.async.cg.shared.global [%0], [%1], 16;" ::"r"(d), "l"(s));
}
#define CP_COMMIT() asm volatile("cp.async.commit_group;" ::: "memory")
#define CP_WAIT_1() asm volatile("cp.async.wait_group 1;" ::: "memory")
#define CP_WAIT_0() asm volatile("cp.async.wait_group 0;" ::: "memory")

#define LDSM_X4(r0, r1, r2, r3, a)                                             \
    asm volatile("ldmatrix.sync.aligned.m8n8.x4.shared.b16 {%0,%1,%2,%3}, [%4];" \
                 : "=r"(r0), "=r"(r1), "=r"(r2), "=r"(r3) : "r"(a))

#define MMA_F16(c0, c1, c2, c3, a0, a1, a2, a3, b0, b1)                        \
    asm volatile("mma.sync.aligned.m16n8k16.row.col.f32.f16.f16.f32 "          \
                 "{%0,%1,%2,%3}, {%4,%5,%6,%7}, {%8,%9}, {%0,%1,%2,%3};"       \
                 : "+f"(c0), "+f"(c1), "+f"(c2), "+f"(c3)                      \
                 : "r"(a0), "r"(a1), "r"(a2), "r"(a3), "r"(b0), "r"(b1))

// ---------------------------------------------------------------------------
// Fused distance GEMM, fp16 tensor cores, 512 threads (16 warps, 4x4 grid,
// warp tile 32x32) for 32 warps/SM occupancy.
//   C[m][n] = xsq[m] + psq[n] - 2 * sum_k A16[m][k] * B16[n][k]
// Smem per tile: row r (128 B), 16B unit u stored at (u ^ (r & 7)).
// ---------------------------------------------------------------------------
__global__ __launch_bounds__(NTH, 2)
void dist_f16_v3_kernel(float* __restrict__ C) {
    extern __shared__ __align__(16) char smem[];
    uint32_t sb0;
    asm("{ .reg .u64 t; cvta.to.shared.u64 t, %1; cvt.u32.u64 %0, t; }"
        : "=r"(sb0) : "l"(smem));
    const uint32_t sb = (sb0 + 127u) & ~127u;

    const int tid  = threadIdx.x;
    const int lane = tid & 31;
    const int warp = tid >> 5;
    const int wm   = warp & 3;       // 4 warps along M -> 32 rows
    const int wn   = warp >> 2;      // 4 warps along N -> 32 cols
    const int bx   = blockIdx.x;     // N tile (0..3)
    const int by   = blockIdx.y;     // M tile (0..127)

    const __half* Ablk = g_a16 + (size_t)by * BM * D_;
    const __half* Bblk = g_b16 + (size_t)bx * BN * D_;

    // loader: 1024 16B units per operand per stage; 2 A + 2 B per thread
    const int lrow = tid >> 3;       // 0..63 (j adds 64)
    const int lu   = tid & 7;
    const uint32_t lsw = (uint32_t)((lu ^ (lrow & 7)) << 4);

    auto load_stage = [&](int s) {
        const uint32_t ab = sb + (uint32_t)(s % STAGES) * STAGEB;
        const uint32_t bb = ab + TILEB;
        const int kf = s * BKH + lu * 8;
        #pragma unroll
        for (int j = 0; j < 2; j++) {
            const int row = lrow + j * 64;
            cp_async16(ab + (uint32_t)row * 128 + lsw,
                       Ablk + (size_t)row * D_ + kf);
            cp_async16(bb + (uint32_t)row * 128 + lsw,
                       Bblk + (size_t)row * D_ + kf);
        }
    };

    // ldmatrix per-lane row/unit components
    const int rA = wm * 32 + (lane & 7) + ((lane >> 3) & 1) * 8;
    const int uA = lane >> 4;
    const int rB = wn * 32 + (lane & 7) + (lane >> 4) * 8;
    const int uB = (lane >> 3) & 1;
    const uint32_t swz = (uint32_t)(lane & 7);

    float c[2][4][4];
    #pragma unroll
    for (int i = 0; i < 2; i++)
        #pragma unroll
        for (int j = 0; j < 4; j++)
            #pragma unroll
            for (int q = 0; q < 4; q++) c[i][j][q] = 0.f;

    load_stage(0); CP_COMMIT();
    load_stage(1); CP_COMMIT();

    for (int s = 0; s < NS; ++s) {
        if (s + 1 < NS) { CP_WAIT_1(); } else { CP_WAIT_0(); }
        __syncthreads();                        // stage s visible; buf(s+2) free
        if (s + 2 < NS) { load_stage(s + 2); CP_COMMIT(); }

        const uint32_t ab = sb + (uint32_t)(s % STAGES) * STAGEB;
        const uint32_t bb = ab + TILEB;

        #pragma unroll
        for (int kk = 0; kk < 4; kk++) {        // 4 x k16 per stage
            uint32_t a[2][4];
            #pragma unroll
            for (int i = 0; i < 2; i++) {
                const uint32_t addr = ab + (uint32_t)(rA + i * 16) * 128
                    + ((((uint32_t)(kk * 2 + uA)) ^ swz) << 4);
                LDSM_X4(a[i][0], a[i][1], a[i][2], a[i][3], addr);
            }
            #pragma unroll
            for (int jp = 0; jp < 2; jp++) {    // 2 n8 tiles per ldmatrix.x4
                uint32_t b0, b1, b2, b3;
                const uint32_t addr = bb + (uint32_t)(rB + jp * 16) * 128
                    + ((((uint32_t)(kk * 2 + uB)) ^ swz) << 4);
                LDSM_X4(b0, b1, b2, b3, addr);
                #pragma unroll
                for (int i = 0; i < 2; i++) {
                    MMA_F16(c[i][jp * 2][0], c[i][jp * 2][1],
                            c[i][jp * 2][2], c[i][jp * 2][3],
                            a[i][0], a[i][1], a[i][2], a[i][3], b0, b1);
                    MMA_F16(c[i][jp * 2 + 1][0], c[i][jp * 2 + 1][1],
                            c[i][jp * 2 + 1][2], c[i][jp * 2 + 1][3],
                            a[i][0], a[i][1], a[i][2], a[i][3], b2, b3);
                }
            }
        }
    }

    // ---- epilogue: dist = xsq + psq - 2*cross ----
    const int g = lane >> 2;
    const int t = lane & 3;
    #pragma unroll
    for (int i = 0; i < 2; i++) {
        const int mg0 = by * BM + wm * 32 + i * 16 + g;
        const float x0 = g_xsq[mg0];
        const float x1 = g_xsq[mg0 + 8];
        float* row0 = C + (size_t)mg0 * P_;
        float* row1 = C + (size_t)(mg0 + 8) * P_;
        #pragma unroll
        for (int j = 0; j < 4; j++) {
            const int ng = bx * BN + wn * 32 + j * 8 + 2 * t;
            const float p0 = g_psq[ng];
            const float p1 = g_psq[ng + 1];
            float2 v0, v1;
            v0.x = x0 + p0 - 2.f * c[i][j][0];
            v0.y = x0 + p1 - 2.f * c[i][j][1];
            v1.x = x1 + p0 - 2.f * c[i][j][2];
            v1.y = x1 + p1 - 2.f * c[i][j][3];
            *reinterpret_cast<float2*>(row0 + ng) = v0;
            *reinterpret_cast<float2*>(row1 + ng) = v1;
        }
    }
}

// ---------------------------------------------------------------------------
extern "C" void kernel_launch(void* const* d_in, const int* in_sizes, int n_in,
                              void* d_out, int out_size) {
    const float* inputs = (const float*)d_in[0];   // [M_, D_]
    const float* protos = (const float*)d_in[1];   // [P_, D_]
    float* out = (float*)d_out;

    // 1) fp16 copies + exact f32 norms + prototype passthrough (single pass)
    prep_kernel<<<(M_ + P_) / 16, 256>>>(inputs, protos, out + (size_t)M_ * P_);

    // 2) fused distance GEMM
    cudaFuncSetAttribute(dist_f16_v3_kernel,
                         cudaFuncAttributeMaxDynamicSharedMemorySize, SMEM_BYTES);
    dim3 grid(P_ / BN, M_ / BM);   // (4, 128)
    dist_f16_v3_kernel<<<grid, NTH, SMEM_BYTES>>>(out);
}

// round 8
// speedup vs baseline: 1.1398x; 1.1398x over previous
#include <cuda_runtime.h>
#include <cuda_fp16.h>
#include <cstdint>

// ---------------------------------------------------------------------------
#define M_ 16384           // B*S token rows
#define P_ 512             // prototypes (= N)
#define D_ 768             // feature dim (= K)
#define BM 128
#define BN 256
#define BKH 64             // K halves per stage (128 B per row)
#define NS (D_ / BKH)      // 12 stages
#define NTH 256
#define STAGES 3
#define ATILEB 16384       // A tile: 128 rows x 128 B
#define BTILEB 32768       // B tile: 256 rows x 128 B
#define STAGEB (ATILEB + BTILEB)
#define SMEM_BYTES (STAGES * STAGEB + 128)

__device__ __half g_a16[(size_t)M_ * D_];
__device__ __half g_b16[(size_t)P_ * D_];
__device__ float  g_xsq[M_];
__device__ float  g_psq[P_];

// ---------------------------------------------------------------------------
// Prep: one pass -> fp16 copies + exact f32 row norms + prototype passthrough.
// ---------------------------------------------------------------------------
__global__ void prep_kernel(const float* __restrict__ X,
                            const float* __restrict__ Pp,
                            float* __restrict__ proto_out) {
    const int r   = threadIdx.x >> 4;
    const int kq  = threadIdx.x & 15;
    const int row = blockIdx.x * 16 + r;
    const float* src;
    __half* dst16;
    float* dstn;
    float* passthru = nullptr;
    if (row < M_) {
        src = X + (size_t)row * D_;  dst16 = g_a16 + (size_t)row * D_;  dstn = g_xsq + row;
    } else {
        const int pr = row - M_;
        src = Pp + (size_t)pr * D_;  dst16 = g_b16 + (size_t)pr * D_;   dstn = g_psq + pr;
        passthru = proto_out + (size_t)pr * D_;
    }
    float s = 0.f;
    #pragma unroll
    for (int i = 0; i < 12; i++) {
        float4 v = *reinterpret_cast<const float4*>(src + i * 64 + kq * 4);
        s = fmaf(v.x, v.x, fmaf(v.y, v.y, fmaf(v.z, v.z, fmaf(v.w, v.w, s))));
        __half2 h01 = __floats2half2_rn(v.x, v.y);
        __half2 h23 = __floats2half2_rn(v.z, v.w);
        *reinterpret_cast<uint2*>(dst16 + i * 64 + kq * 4) =
            make_uint2(*reinterpret_cast<uint32_t*>(&h01),
                       *reinterpret_cast<uint32_t*>(&h23));
        if (passthru) *reinterpret_cast<float4*>(passthru + i * 64 + kq * 4) = v;
    }
    #pragma unroll
    for (int o = 8; o; o >>= 1) s += __shfl_xor_sync(0xffffffffu, s, o);
    if (kq == 0) *dstn = s;
}

// ---------------------------------------------------------------------------
__device__ __forceinline__ void cp_async16(uint32_t d, const void* s) {
    asm volatile("cp.async.cg.shared.global [%0], [%1], 16;" ::"r"(d), "l"(s));
}
#define CP_COMMIT() asm volatile("cp.async.commit_group;" ::: "memory")
#define CP_WAIT_1() asm volatile("cp.async.wait_group 1;" ::: "memory")
#define CP_WAIT_0() asm volatile("cp.async.wait_group 0;" ::: "memory")

#define LDSM_X4(r0, r1, r2, r3, a)                                             \
    asm volatile("ldmatrix.sync.aligned.m8n8.x4.shared.b16 {%0,%1,%2,%3}, [%4];" \
                 : "=r"(r0), "=r"(r1), "=r"(r2), "=r"(r3) : "r"(a))

#define MMA_F16(c0, c1, c2, c3, a0, a1, a2, a3, b0, b1)                        \
    asm volatile("mma.sync.aligned.m16n8k16.row.col.f32.f16.f16.f32 "          \
                 "{%0,%1,%2,%3}, {%4,%5,%6,%7}, {%8,%9}, {%0,%1,%2,%3};"       \
                 : "+f"(c0), "+f"(c1), "+f"(c2), "+f"(c3)                      \
                 : "r"(a0), "r"(a1), "r"(a2), "r"(a3), "r"(b0), "r"(b1))

// ---------------------------------------------------------------------------
// Fused distance GEMM, fp16 tensor cores. 8 warps (2 M x 4 N), warp tile
// 64x64, CTA tile 128x256. Double-buffered fragments inside each stage.
//   C[m][n] = xsq[m] + psq[n] - 2 * sum_k A16[m][k] * B16[n][k]
// Smem per tile: row r (128 B), 16B unit u stored at (u ^ (r & 7)).
// ---------------------------------------------------------------------------
__global__ __launch_bounds__(NTH, 1)
void dist_f16_v4_kernel(float* __restrict__ C) {
    extern __shared__ __align__(16) char smem[];
    uint32_t sb0;
    asm("{ .reg .u64 t; cvta.to.shared.u64 t, %1; cvt.u32.u64 %0, t; }"
        : "=r"(sb0) : "l"(smem));
    const uint32_t sb = (sb0 + 127u) & ~127u;

    const int tid  = threadIdx.x;
    const int lane = tid & 31;
    const int warp = tid >> 5;
    const int wm   = warp & 1;       // 2 warps along M -> 64 rows each
    const int wn   = warp >> 1;      // 4 warps along N -> 64 cols each
    const int bx   = blockIdx.x;     // N tile (0..1)
    const int by   = blockIdx.y;     // M tile (0..127)

    const __half* Ablk = g_a16 + (size_t)by * BM * D_;
    const __half* Bblk = g_b16 + (size_t)bx * BN * D_;

    // loader: A 1024 + B 2048 16B-units per stage -> 4 + 8 per thread
    const int lrow = tid >> 3;       // 0..31 (j adds 32)
    const int lu   = tid & 7;
    const uint32_t lsw = (uint32_t)((lu ^ (lrow & 7)) << 4);

    auto load_stage = [&](int s) {
        const uint32_t ab = sb + (uint32_t)(s % STAGES) * STAGEB;
        const uint32_t bb = ab + ATILEB;
        const int kf = s * BKH + lu * 8;
        #pragma unroll
        for (int j = 0; j < 4; j++) {
            const int row = lrow + j * 32;
            cp_async16(ab + (uint32_t)row * 128 + lsw,
                       Ablk + (size_t)row * D_ + kf);
        }
        #pragma unroll
        for (int j = 0; j < 8; j++) {
            const int row = lrow + j * 32;
            cp_async16(bb + (uint32_t)row * 128 + lsw,
                       Bblk + (size_t)row * D_ + kf);
        }
    };

    // ldmatrix per-lane components
    const int rA = wm * 64 + (lane & 7) + ((lane >> 3) & 1) * 8;  // + i*16
    const int uA = lane >> 4;
    const int rB = wn * 64 + (lane & 7) + (lane >> 4) * 8;        // + jp*16
    const int uB = (lane >> 3) & 1;
    const uint32_t swz = (uint32_t)(lane & 7);

    float c[4][8][4];
    #pragma unroll
    for (int i = 0; i < 4; i++)
        #pragma unroll
        for (int j = 0; j < 8; j++)
            #pragma unroll
            for (int q = 0; q < 4; q++) c[i][j][q] = 0.f;

    uint32_t a[2][4][4], b[2][4][4];     // double-buffered fragments

    auto frag_load = [&](int fb, uint32_t ab, uint32_t bb, int kk) {
        #pragma unroll
        for (int i = 0; i < 4; i++) {
            const uint32_t addr = ab + (uint32_t)(rA + i * 16) * 128
                + ((((uint32_t)(kk * 2 + uA)) ^ swz) << 4);
            LDSM_X4(a[fb][i][0], a[fb][i][1], a[fb][i][2], a[fb][i][3], addr);
        }
        #pragma unroll
        for (int jp = 0; jp < 4; jp++) {
            const uint32_t addr = bb + (uint32_t)(rB + jp * 16) * 128
                + ((((uint32_t)(kk * 2 + uB)) ^ swz) << 4);
            LDSM_X4(b[fb][jp][0], b[fb][jp][1], b[fb][jp][2], b[fb][jp][3], addr);
        }
    };

    load_stage(0); CP_COMMIT();
    load_stage(1); CP_COMMIT();

    for (int s = 0; s < NS; ++s) {
        if (s + 1 < NS) { CP_WAIT_1(); } else { CP_WAIT_0(); }
        __syncthreads();                        // stage s visible; buf(s+2) free
        if (s + 2 < NS) { load_stage(s + 2); CP_COMMIT(); }

        const uint32_t ab = sb + (uint32_t)(s % STAGES) * STAGEB;
        const uint32_t bb = ab + ATILEB;

        frag_load(0, ab, bb, 0);
        #pragma unroll
        for (int kk = 0; kk < 4; kk++) {        // 4 x k16 per stage
            const int fb = kk & 1;
            if (kk + 1 < 4) frag_load(fb ^ 1, ab, bb, kk + 1);
            #pragma unroll
            for (int i = 0; i < 4; i++) {
                #pragma unroll
                for (int jp = 0; jp < 4; jp++) {
                    MMA_F16(c[i][jp * 2][0], c[i][jp * 2][1],
                            c[i][jp * 2][2], c[i][jp * 2][3],
                            a[fb][i][0], a[fb][i][1], a[fb][i][2], a[fb][i][3],
                            b[fb][jp][0], b[fb][jp][1]);
                    MMA_F16(c[i][jp * 2 + 1][0], c[i][jp * 2 + 1][1],
                            c[i][jp * 2 + 1][2], c[i][jp * 2 + 1][3],
                            a[fb][i][0], a[fb][i][1], a[fb][i][2], a[fb][i][3],
                            b[fb][jp][2], b[fb][jp][3]);
                }
            }
        }
    }

    // ---- epilogue: dist = xsq + psq - 2*cross ----
    const int g = lane >> 2;
    const int t = lane & 3;
    #pragma unroll
    for (int i = 0; i < 4; i++) {
        const int mg0 = by * BM + wm * 64 + i * 16 + g;
        const float x0 = g_xsq[mg0];
        const float x1 = g_xsq[mg0 + 8];
        float* row0 = C + (size_t)mg0 * P_;
        float* row1 = C + (size_t)(mg0 + 8) * P_;
        #pragma unroll
        for (int j = 0; j < 8; j++) {
            const int ng = bx * BN + wn * 64 + j * 8 + 2 * t;
            const float p0 = g_psq[ng];
            const float p1 = g_psq[ng + 1];
            float2 v0, v1;
            v0.x = x0 + p0 - 2.f * c[i][j][0];
            v0.y = x0 + p1 - 2.f * c[i][j][1];
            v1.x = x1 + p0 - 2.f * c[i][j][2];
            v1.y = x1 + p1 - 2.f * c[i][j][3];
            *reinterpret_cast<float2*>(row0 + ng) = v0;
            *reinterpret_cast<float2*>(row1 + ng) = v1;
        }
    }
}

// ---------------------------------------------------------------------------
extern "C" void kernel_launch(void* const* d_in, const int* in_sizes, int n_in,
                              void* d_out, int out_size) {
    const float* inputs = (const float*)d_in[0];   // [M_, D_]
    const float* protos = (const float*)d_in[1];   // [P_, D_]
    float* out = (float*)d_out;

    // 1) fp16 copies + exact f32 norms + prototype passthrough (single pass)
    prep_kernel<<<(M_ + P_) / 16, 256>>>(inputs, protos, out + (size_t)M_ * P_);

    // 2) fused distance GEMM
    cudaFuncSetAttribute(dist_f16_v4_kernel,
                         cudaFuncAttributeMaxDynamicSharedMemorySize, SMEM_BYTES);
    dim3 grid(P_ / BN, M_ / BM);   // (2, 128)
    dist_f16_v4_kernel<<<grid, NTH, SMEM_BYTES>>>(out);
}

// round 9
// speedup vs baseline: 1.1735x; 1.0296x over previous
#include <cuda_runtime.h>
#include <cuda_fp16.h>
#include <cstdint>

// ---------------------------------------------------------------------------
#define M_ 16384           // B*S token rows
#define P_ 512             // prototypes (= N)
#define D_ 768             // feature dim (= K)
#define BM 128
#define BN 128
#define BKH 64             // K halves per stage (128 B per row)
#define NS (D_ / BKH)      // 12 stages
#define NTH 128            // 4 warps
#define STAGES 3
#define ATILEB 16384       // A tile: 128 rows x 128 B
#define BTILEB 16384       // B tile: 128 rows x 128 B
#define STAGEB (ATILEB + BTILEB)
#define SMEM_BYTES (STAGES * STAGEB + 128)

__device__ __half g_a16[(size_t)M_ * D_];
__device__ __half g_b16[(size_t)P_ * D_];
__device__ float  g_xsq[M_];
__device__ float  g_psq[P_];

// ---------------------------------------------------------------------------
// Prep: one pass -> fp16 copies + exact f32 row norms + prototype passthrough.
// ---------------------------------------------------------------------------
__global__ void prep_kernel(const float* __restrict__ X,
                            const float* __restrict__ Pp,
                            float* __restrict__ proto_out) {
    const int r   = threadIdx.x >> 4;
    const int kq  = threadIdx.x & 15;
    const int row = blockIdx.x * 16 + r;
    const float* src;
    __half* dst16;
    float* dstn;
    float* passthru = nullptr;
    if (row < M_) {
        src = X + (size_t)row * D_;  dst16 = g_a16 + (size_t)row * D_;  dstn = g_xsq + row;
    } else {
        const int pr = row - M_;
        src = Pp + (size_t)pr * D_;  dst16 = g_b16 + (size_t)pr * D_;   dstn = g_psq + pr;
        passthru = proto_out + (size_t)pr * D_;
    }
    float s = 0.f;
    #pragma unroll
    for (int i = 0; i < 12; i++) {
        float4 v = *reinterpret_cast<const float4*>(src + i * 64 + kq * 4);
        s = fmaf(v.x, v.x, fmaf(v.y, v.y, fmaf(v.z, v.z, fmaf(v.w, v.w, s))));
        __half2 h01 = __floats2half2_rn(v.x, v.y);
        __half2 h23 = __floats2half2_rn(v.z, v.w);
        *reinterpret_cast<uint2*>(dst16 + i * 64 + kq * 4) =
            make_uint2(*reinterpret_cast<uint32_t*>(&h01),
                       *reinterpret_cast<uint32_t*>(&h23));
        if (passthru) *reinterpret_cast<float4*>(passthru + i * 64 + kq * 4) = v;
    }
    #pragma unroll
    for (int o = 8; o; o >>= 1) s += __shfl_xor_sync(0xffffffffu, s, o);
    if (kq == 0) *dstn = s;
}

// ---------------------------------------------------------------------------
__device__ __forceinline__ void cp_async16(uint32_t d, const void* s) {
    asm volatile("cp.async.cg.shared.global [%0], [%1], 16;" ::"r"(d), "l"(s));
}
#define CP_COMMIT() asm volatile("cp.async.commit_group;" ::: "memory")
#define CP_WAIT_1() asm volatile("cp.async.wait_group 1;" ::: "memory")
#define CP_WAIT_0() asm volatile("cp.async.wait_group 0;" ::: "memory")

#define LDSM_X4(r0, r1, r2, r3, a)                                             \
    asm volatile("ldmatrix.sync.aligned.m8n8.x4.shared.b16 {%0,%1,%2,%3}, [%4];" \
                 : "=r"(r0), "=r"(r1), "=r"(r2), "=r"(r3) : "r"(a))

#define MMA_F16(c0, c1, c2, c3, a0, a1, a2, a3, b0, b1)                        \
    asm volatile("mma.sync.aligned.m16n8k16.row.col.f32.f16.f16.f32 "          \
                 "{%0,%1,%2,%3}, {%4,%5,%6,%7}, {%8,%9}, {%0,%1,%2,%3};"       \
                 : "+f"(c0), "+f"(c1), "+f"(c2), "+f"(c3)                      \
                 : "r"(a0), "r"(a1), "r"(a2), "r"(a3), "r"(b0), "r"(b1))

// ---------------------------------------------------------------------------
// Fused distance GEMM, fp16 tensor cores. 4 warps (2 M x 2 N), warp tile
// 64x64, CTA tile 128x128, 128 threads, 2 CTAs/SM.
//   C[m][n] = xsq[m] + psq[n] - 2 * sum_k A16[m][k] * B16[n][k]
// Smem per tile: row r (128 B), 16B unit u stored at (u ^ (r & 7)).
// ---------------------------------------------------------------------------
__global__ __launch_bounds__(NTH, 2)
void dist_f16_v5_kernel(float* __restrict__ C) {
    extern __shared__ __align__(16) char smem[];
    uint32_t sb0;
    asm("{ .reg .u64 t; cvta.to.shared.u64 t, %1; cvt.u32.u64 %0, t; }"
        : "=r"(sb0) : "l"(smem));
    const uint32_t sb = (sb0 + 127u) & ~127u;

    const int tid  = threadIdx.x;
    const int lane = tid & 31;
    const int warp = tid >> 5;
    const int wm   = warp & 1;       // 2 warps along M -> 64 rows each
    const int wn   = warp >> 1;      // 2 warps along N -> 64 cols each
    const int bx   = blockIdx.x;     // N tile (0..3)
    const int by   = blockIdx.y;     // M tile (0..127)

    const __half* Ablk = g_a16 + (size_t)by * BM * D_;
    const __half* Bblk = g_b16 + (size_t)bx * BN * D_;

    // loader: A 1024 + B 1024 16B-units per stage -> 8 + 8 per thread
    const int lrow = tid >> 3;       // 0..15 (j adds 16)
    const int lu   = tid & 7;
    const uint32_t lsw = (uint32_t)((lu ^ (lrow & 7)) << 4);

    auto load_stage = [&](int s) {
        const uint32_t ab = sb + (uint32_t)(s % STAGES) * STAGEB;
        const uint32_t bb = ab + ATILEB;
        const int kf = s * BKH + lu * 8;
        #pragma unroll
        for (int j = 0; j < 8; j++) {
            const int row = lrow + j * 16;
            cp_async16(ab + (uint32_t)row * 128 + lsw,
                       Ablk + (size_t)row * D_ + kf);
            cp_async16(bb + (uint32_t)row * 128 + lsw,
                       Bblk + (size_t)row * D_ + kf);
        }
    };

    // ldmatrix per-lane components
    const int rA = wm * 64 + (lane & 7) + ((lane >> 3) & 1) * 8;  // + i*16
    const int uA = lane >> 4;
    const int rB = wn * 64 + (lane & 7) + (lane >> 4) * 8;        // + jp*16
    const int uB = (lane >> 3) & 1;
    const uint32_t swz = (uint32_t)(lane & 7);

    float c[4][8][4];
    #pragma unroll
    for (int i = 0; i < 4; i++)
        #pragma unroll
        for (int j = 0; j < 8; j++)
            #pragma unroll
            for (int q = 0; q < 4; q++) c[i][j][q] = 0.f;

    uint32_t a[2][4][4], b[2][4][4];     // double-buffered fragments

    auto frag_load = [&](int fb, uint32_t ab, uint32_t bb, int kk) {
        #pragma unroll
        for (int i = 0; i < 4; i++) {
            const uint32_t addr = ab + (uint32_t)(rA + i * 16) * 128
                + ((((uint32_t)(kk * 2 + uA)) ^ swz) << 4);
            LDSM_X4(a[fb][i][0], a[fb][i][1], a[fb][i][2], a[fb][i][3], addr);
        }
        #pragma unroll
        for (int jp = 0; jp < 4; jp++) {
            const uint32_t addr = bb + (uint32_t)(rB + jp * 16) * 128
                + ((((uint32_t)(kk * 2 + uB)) ^ swz) << 4);
            LDSM_X4(b[fb][jp][0], b[fb][jp][1], b[fb][jp][2], b[fb][jp][3], addr);
        }
    };

    load_stage(0); CP_COMMIT();
    load_stage(1); CP_COMMIT();

    for (int s = 0; s < NS; ++s) {
        if (s + 1 < NS) { CP_WAIT_1(); } else { CP_WAIT_0(); }
        __syncthreads();                        // stage s visible; buf(s+2) free
        if (s + 2 < NS) { load_stage(s + 2); CP_COMMIT(); }

        const uint32_t ab = sb + (uint32_t)(s % STAGES) * STAGEB;
        const uint32_t bb = ab + ATILEB;

        frag_load(0, ab, bb, 0);
        #pragma unroll
        for (int kk = 0; kk < 4; kk++) {        // 4 x k16 per stage
            const int fb = kk & 1;
            if (kk + 1 < 4) frag_load(fb ^ 1, ab, bb, kk + 1);
            #pragma unroll
            for (int i = 0; i < 4; i++) {
                #pragma unroll
                for (int jp = 0; jp < 4; jp++) {
                    MMA_F16(c[i][jp * 2][0], c[i][jp * 2][1],
                            c[i][jp * 2][2], c[i][jp * 2][3],
                            a[fb][i][0], a[fb][i][1], a[fb][i][2], a[fb][i][3],
                            b[fb][jp][0], b[fb][jp][1]);
                    MMA_F16(c[i][jp * 2 + 1][0], c[i][jp * 2 + 1][1],
                            c[i][jp * 2 + 1][2], c[i][jp * 2 + 1][3],
                            a[fb][i][0], a[fb][i][1], a[fb][i][2], a[fb][i][3],
                            b[fb][jp][2], b[fb][jp][3]);
                }
            }
        }
    }

    // ---- epilogue: dist = xsq + psq - 2*cross ----
    const int g = lane >> 2;
    const int t = lane & 3;
    #pragma unroll
    for (int i = 0; i < 4; i++) {
        const int mg0 = by * BM + wm * 64 + i * 16 + g;
        const float x0 = g_xsq[mg0];
        const float x1 = g_xsq[mg0 + 8];
        float* row0 = C + (size_t)mg0 * P_;
        float* row1 = C + (size_t)(mg0 + 8) * P_;
        #pragma unroll
        for (int j = 0; j < 8; j++) {
            const int ng = bx * BN + wn * 64 + j * 8 + 2 * t;
            const float p0 = g_psq[ng];
            const float p1 = g_psq[ng + 1];
            float2 v0, v1;
            v0.x = x0 + p0 - 2.f * c[i][j][0];
            v0.y = x0 + p1 - 2.f * c[i][j][1];
            v1.x = x1 + p0 - 2.f * c[i][j][2];
            v1.y = x1 + p1 - 2.f * c[i][j][3];
            *reinterpret_cast<float2*>(row0 + ng) = v0;
            *reinterpret_cast<float2*>(row1 + ng) = v1;
        }
    }
}

// ---------------------------------------------------------------------------
extern "C" void kernel_launch(void* const* d_in, const int* in_sizes, int n_in,
                              void* d_out, int out_size) {
    const float* inputs = (const float*)d_in[0];   // [M_, D_]
    const float* protos = (const float*)d_in[1];   // [P_, D_]
    float* out = (float*)d_out;

    // 1) fp16 copies + exact f32 norms + prototype passthrough (single pass)
    prep_kernel<<<(M_ + P_) / 16, 256>>>(inputs, protos, out + (size_t)M_ * P_);

    // 2) fused distance GEMM
    cudaFuncSetAttribute(dist_f16_v5_kernel,
                         cudaFuncAttributeMaxDynamicSharedMemorySize, SMEM_BYTES);
    dim3 grid(P_ / BN, M_ / BM);   // (4, 128)
    dist_f16_v5_kernel<<<grid, NTH, SMEM_BYTES>>>(out);
}